// round 2
// baseline (speedup 1.0000x reference)
#include <cuda_runtime.h>
#include <math.h>

#define BB 8192
#define DD 384
#define EE 1024
#define RR 8
#define HH 64

// ---------------- device scratch (no dynamic allocation allowed) ----------------
__device__ float g_evt[RR * HH * EE];     // ev transposed: [r][h][e]   (2 MB)
__device__ float g_gw[BB * 2];            // gate weights per (token, k-slot)
__device__ int   g_cnt[RR];               // per-router assignment counts
__device__ int   g_list[RR * BB];         // per-router assignment codes (b*2 + k)
__device__ float g_probs[BB * 2 * EE];    // gate-weighted softmax rows (64 MB)
__device__ float g_sumP[RR];
__device__ float g_sumM[RR];

// ---------------- f32x2 helpers (full-rate fp32 on sm_103a) ----------------
__device__ __forceinline__ unsigned long long pk2(float a, float b) {
    unsigned long long r;
    asm("mov.b64 %0, {%1,%2};" : "=l"(r) : "f"(a), "f"(b));
    return r;
}
__device__ __forceinline__ void upk2(unsigned long long v, float& lo, float& hi) {
    asm("mov.b64 {%0,%1}, %2;" : "=f"(lo), "=f"(hi) : "l"(v));
}
__device__ __forceinline__ unsigned long long fma2(unsigned long long a,
                                                   unsigned long long b,
                                                   unsigned long long c) {
    unsigned long long d;
    asm("fma.rn.f32x2 %0, %1, %2, %3;" : "=l"(d) : "l"(a), "l"(b), "l"(c));
    return d;
}

// ---------------- kernel 0: init ----------------
__global__ void k_init() {
    int t = threadIdx.x;
    if (t < RR) { g_cnt[t] = 0; g_sumP[t] = 0.f; g_sumM[t] = 0.f; }
}

// ---------------- kernel 1: gate (warp per token) ----------------
__global__ void __launch_bounds__(256) k_gate(const float* __restrict__ x,
                                              const float* __restrict__ gw,
                                              const float* __restrict__ gb) {
    __shared__ float sP[RR], sM[RR];
    int tid = threadIdx.x;
    if (tid < RR) { sP[tid] = 0.f; sM[tid] = 0.f; }
    __syncthreads();

    int warp = tid >> 5, lane = tid & 31;
    int b = blockIdx.x * 8 + warp;

    float acc[RR];
#pragma unroll
    for (int r = 0; r < RR; r++) acc[r] = 0.f;
    const float* xr = x + b * DD;
    for (int d = lane; d < DD; d += 32) {
        float xv = xr[d];
        const float4* g4 = (const float4*)(gw + d * RR);
        float4 a = g4[0], c = g4[1];
        acc[0] += xv * a.x; acc[1] += xv * a.y; acc[2] += xv * a.z; acc[3] += xv * a.w;
        acc[4] += xv * c.x; acc[5] += xv * c.y; acc[6] += xv * c.z; acc[7] += xv * c.w;
    }
#pragma unroll
    for (int r = 0; r < RR; r++)
#pragma unroll
        for (int o = 16; o; o >>= 1) acc[r] += __shfl_xor_sync(0xffffffffu, acc[r], o);

    if (lane == 0) {
        float lg[RR];
#pragma unroll
        for (int r = 0; r < RR; r++) lg[r] = acc[r] + gb[r];
        // top-1 (first occurrence on ties, matching lax.top_k)
        int i0 = 0; float v0 = lg[0];
#pragma unroll
        for (int r = 1; r < RR; r++) if (lg[r] > v0) { v0 = lg[r]; i0 = r; }
        // top-2
        int i1 = -1; float v1 = -3.0e38f;
#pragma unroll
        for (int r = 0; r < RR; r++) if (r != i0 && lg[r] > v1) { v1 = lg[r]; i1 = r; }

        // full softmax for aux loss
        float s = 0.f, pr[RR];
#pragma unroll
        for (int r = 0; r < RR; r++) { pr[r] = expf(lg[r] - v0); s += pr[r]; }
        float inv = 1.f / s;
#pragma unroll
        for (int r = 0; r < RR; r++) atomicAdd(&sP[r], pr[r] * inv);
        atomicAdd(&sM[i0], 1.f);
        atomicAdd(&sM[i1], 1.f);

        // softmax over the two top logits
        float e1 = expf(v1 - v0);
        float den = 1.f / (1.f + e1);
        g_gw[b * 2 + 0] = den;
        g_gw[b * 2 + 1] = e1 * den;

        int p0 = atomicAdd(&g_cnt[i0], 1); g_list[i0 * BB + p0] = b * 2 + 0;
        int p1 = atomicAdd(&g_cnt[i1], 1); g_list[i1 * BB + p1] = b * 2 + 1;
    }
    __syncthreads();
    if (tid < RR) { atomicAdd(&g_sumP[tid], sP[tid]); atomicAdd(&g_sumM[tid], sM[tid]); }
}

// ---------------- kernel 2: ev = l2norm(re @ Vw[r] + Vb[r]), stored [r][h][e] ----------------
__global__ void __launch_bounds__(256) k_ev(const float* __restrict__ re,
                                            const float* __restrict__ Vw,
                                            const float* __restrict__ Vb) {
    __shared__ float re_s[16 * DD];       // 24 KB
    __shared__ float evl[16][HH + 1];
    __shared__ float s_rn[16];

    int r = blockIdx.y;
    int ebase = blockIdx.x * 16;
    int tid = threadIdx.x;

    for (int idx = tid; idx < 16 * DD; idx += 256)
        re_s[idx] = re[(ebase + idx / DD) * DD + idx % DD];
    __syncthreads();

    int h = tid & 63, eg = tid >> 6;
    float acc[4];
    float bias = Vb[r * HH + h];
#pragma unroll
    for (int j = 0; j < 4; j++) acc[j] = bias;
    const float* Vr = Vw + r * DD * HH;
    for (int d = 0; d < DD; d++) {
        float v = Vr[d * HH + h];
#pragma unroll
        for (int j = 0; j < 4; j++) acc[j] += re_s[(eg * 4 + j) * DD + d] * v;
    }
#pragma unroll
    for (int j = 0; j < 4; j++) evl[eg * 4 + j][h] = acc[j];
    __syncthreads();
    if (tid < 16) {
        float ss = 0.f;
        for (int hh = 0; hh < HH; hh++) { float v = evl[tid][hh]; ss += v * v; }
        s_rn[tid] = 1.f / fmaxf(sqrtf(ss), 1e-12f);
    }
    __syncthreads();
#pragma unroll
    for (int j = 0; j < 4; j++)
        g_evt[(r * HH + h) * EE + ebase + eg * 4 + j] = acc[j] * s_rn[eg * 4 + j];
}

// ---------------- kernel 3: main — xu + scores + softmax + weighted store ----------------
__global__ void __launch_bounds__(256) k_main(const float* __restrict__ x,
                                              const float* __restrict__ Uw,
                                              const float* __restrict__ Ub) {
    __shared__ float x_s[16 * DD];        // 24 KB
    __shared__ float xu_p[HH][18];        // h-major, padded (4.5 KB)
    __shared__ float s_rn[16];
    __shared__ float s_w[16];
    __shared__ int   s_code[16];
    __shared__ float red[8][16];
    __shared__ float rowmax[16];
    __shared__ float s_scale[16];

    int r = blockIdx.y;
    int cnt = g_cnt[r];
    int base = blockIdx.x * 16;
    if (base >= cnt) return;
    int nt = min(16, cnt - base);
    int tid = threadIdx.x;

    if (tid < 16) {
        int code = (tid < nt) ? g_list[r * BB + base + tid] : -1;
        s_code[tid] = code;
        s_w[tid] = (code >= 0) ? g_gw[code] : 0.f;
    }
    __syncthreads();
    for (int idx = tid; idx < 16 * DD; idx += 256) {
        int t = idx / DD;
        int code = s_code[t];
        x_s[idx] = (code >= 0) ? x[(code >> 1) * DD + idx % DD] : 0.f;
    }
    __syncthreads();

    // ---- phase 1: xu = l2norm(x @ Uw[r] + Ub[r]) for 16 tokens ----
    {
        int h = tid & 63, eg = tid >> 6;
        float acc[4];
        float bias = Ub[r * HH + h];
#pragma unroll
        for (int j = 0; j < 4; j++) acc[j] = bias;
        const float* Ur = Uw + r * DD * HH;
        for (int d = 0; d < DD; d++) {
            float u = Ur[d * HH + h];
#pragma unroll
            for (int j = 0; j < 4; j++) acc[j] += x_s[(eg * 4 + j) * DD + d] * u;
        }
#pragma unroll
        for (int j = 0; j < 4; j++) xu_p[h][eg * 4 + j] = acc[j];
    }
    __syncthreads();
    if (tid < 16) {
        float ss = 0.f;
        for (int hh = 0; hh < HH; hh++) { float v = xu_p[hh][tid]; ss += v * v; }
        s_rn[tid] = 1.f / fmaxf(sqrtf(ss), 1e-12f);
    }
    __syncthreads();
    for (int idx = tid; idx < HH * 16; idx += 256) {
        int hh = idx >> 4, t = idx & 15;
        xu_p[hh][t] *= s_rn[t];
    }
    __syncthreads();

    // ---- phase 2: scores[16][1024] via packed f32x2 FMA ----
    unsigned long long acc2[8][4];
#pragma unroll
    for (int tp = 0; tp < 8; tp++)
#pragma unroll
        for (int j = 0; j < 4; j++) acc2[tp][j] = 0ULL;

    int e0 = tid * 4;
    const float* evr = g_evt + r * HH * EE;
#pragma unroll 4
    for (int h = 0; h < HH; h++) {
        float4 ev4 = *(const float4*)(evr + h * EE + e0);
        unsigned long long bx = pk2(ev4.x, ev4.x);
        unsigned long long by = pk2(ev4.y, ev4.y);
        unsigned long long bz = pk2(ev4.z, ev4.z);
        unsigned long long bw = pk2(ev4.w, ev4.w);
        const unsigned long long* xp = (const unsigned long long*)&xu_p[h][0];
#pragma unroll
        for (int tp = 0; tp < 8; tp++) {
            unsigned long long xs = xp[tp];
            acc2[tp][0] = fma2(xs, bx, acc2[tp][0]);
            acc2[tp][1] = fma2(xs, by, acc2[tp][1]);
            acc2[tp][2] = fma2(xs, bz, acc2[tp][2]);
            acc2[tp][3] = fma2(xs, bw, acc2[tp][3]);
        }
    }

    // ---- row max reduction (16 rows over 256 threads) ----
    int lane = tid & 31, w = tid >> 5;
    {
        float lmax[16];
#pragma unroll
        for (int t = 0; t < 16; t++) lmax[t] = -3.0e38f;
#pragma unroll
        for (int tp = 0; tp < 8; tp++)
#pragma unroll
            for (int j = 0; j < 4; j++) {
                float lo, hi;
                upk2(acc2[tp][j], lo, hi);
                lmax[2 * tp]     = fmaxf(lmax[2 * tp], lo);
                lmax[2 * tp + 1] = fmaxf(lmax[2 * tp + 1], hi);
            }
#pragma unroll
        for (int t = 0; t < 16; t++)
#pragma unroll
            for (int o = 16; o; o >>= 1)
                lmax[t] = fmaxf(lmax[t], __shfl_xor_sync(0xffffffffu, lmax[t], o));
        if (lane == 0)
#pragma unroll
            for (int t = 0; t < 16; t++) red[w][t] = lmax[t];
    }
    __syncthreads();
    if (tid < 16) {
        float m = red[0][tid];
#pragma unroll
        for (int ww = 1; ww < 8; ww++) m = fmaxf(m, red[ww][tid]);
        rowmax[tid] = m;
    }
    __syncthreads();

    // ---- exp + row sum ----
    {
        float lsum[16];
#pragma unroll
        for (int t = 0; t < 16; t++) lsum[t] = 0.f;
#pragma unroll
        for (int tp = 0; tp < 8; tp++) {
            float m0 = rowmax[2 * tp], m1 = rowmax[2 * tp + 1];
#pragma unroll
            for (int j = 0; j < 4; j++) {
                float lo, hi;
                upk2(acc2[tp][j], lo, hi);
                float elo = __expf(lo - m0);
                float ehi = __expf(hi - m1);
                lsum[2 * tp]     += elo;
                lsum[2 * tp + 1] += ehi;
                acc2[tp][j] = pk2(elo, ehi);
            }
        }
#pragma unroll
        for (int t = 0; t < 16; t++)
#pragma unroll
            for (int o = 16; o; o >>= 1)
                lsum[t] += __shfl_xor_sync(0xffffffffu, lsum[t], o);
        if (lane == 0)
#pragma unroll
            for (int t = 0; t < 16; t++) red[w][t] = lsum[t];
    }
    __syncthreads();
    if (tid < 16) {
        float s = 0.f;
#pragma unroll
        for (int ww = 0; ww < 8; ww++) s += red[ww][tid];
        s_scale[tid] = s_w[tid] / s;        // gate weight folded into normalization
    }
    __syncthreads();

    // ---- store gate-weighted probability rows ----
#pragma unroll
    for (int tp = 0; tp < 8; tp++) {
        int t0 = 2 * tp, t1 = 2 * tp + 1;
        float sc0 = s_scale[t0], sc1 = s_scale[t1];
        float4 olo, ohi;
        float lo, hi;
        upk2(acc2[tp][0], lo, hi); olo.x = lo * sc0; ohi.x = hi * sc1;
        upk2(acc2[tp][1], lo, hi); olo.y = lo * sc0; ohi.y = hi * sc1;
        upk2(acc2[tp][2], lo, hi); olo.z = lo * sc0; ohi.z = hi * sc1;
        upk2(acc2[tp][3], lo, hi); olo.w = lo * sc0; ohi.w = hi * sc1;
        if (t0 < nt) *(float4*)(g_probs + (long)s_code[t0] * EE + e0) = olo;
        if (t1 < nt) *(float4*)(g_probs + (long)s_code[t1] * EE + e0) = ohi;
    }
}

// ---------------- kernel 4: combine rows, inverse-CDF sample, log-prob ----------------
__global__ void __launch_bounds__(256) k_sample(const float* __restrict__ rnd,
                                                float* __restrict__ out) {
    __shared__ float wsum[8];
    __shared__ int s_min;
    int b = blockIdx.x, tid = threadIdx.x;
    if (tid == 0) s_min = 0x7fffffff;

    const float4* p0 = (const float4*)(g_probs + (long)(b * 2 + 0) * EE);
    const float4* p1 = (const float4*)(g_probs + (long)(b * 2 + 1) * EE);
    float4 a = p0[tid], c = p1[tid];
    float p[4] = { a.x + c.x, a.y + c.y, a.z + c.z, a.w + c.w };

    float c0 = p[0], c1 = c0 + p[1], c2 = c1 + p[2], c3 = c2 + p[3];
    float tsum = c3;

    int lane = tid & 31, w = tid >> 5;
    float sc = tsum;
#pragma unroll
    for (int o = 1; o < 32; o <<= 1) {
        float v = __shfl_up_sync(0xffffffffu, sc, o);
        if (lane >= o) sc += v;
    }
    if (lane == 31) wsum[w] = sc;
    __syncthreads();                          // also covers s_min init
    float woff = 0.f;
    for (int ww = 0; ww < w; ww++) woff += wsum[ww];
    float excl = woff + sc - tsum;

    float rv = rnd[b];
    float cums[4] = { excl + c0, excl + c1, excl + c2, excl + c3 };
    int found = -1;
#pragma unroll
    for (int j = 0; j < 4; j++)
        if (found < 0 && cums[j] > rv) found = tid * 4 + j;
    if (found >= 0) atomicMin(&s_min, found);
    __syncthreads();
    int sel = (s_min == 0x7fffffff) ? 0 : s_min;
    if (tid == (sel >> 2)) out[BB + b] = logf(p[sel & 3]);
    if (tid == 0) out[b] = (float)sel;
}

// ---------------- kernel 5: aux loss ----------------
__global__ void k_aux(float* __restrict__ out) {
    if (threadIdx.x == 0 && blockIdx.x == 0) {
        float s = 0.f;
#pragma unroll
        for (int r = 0; r < RR; r++) s += g_sumP[r] * g_sumM[r];
        out[2 * BB] = (float)RR * 0.05f * s / ((float)BB * (float)BB);
    }
}

// ---------------- launch ----------------
extern "C" void kernel_launch(void* const* d_in, const int* in_sizes, int n_in,
                              void* d_out, int out_size) {
    const float* x   = (const float*)d_in[0];  // [B, 384]
    const float* re  = (const float*)d_in[1];  // [1024, 384]
    const float* rnd = (const float*)d_in[2];  // [B, 1]
    const float* gw  = (const float*)d_in[3];  // [384, 8]
    const float* gb  = (const float*)d_in[4];  // [8]
    const float* Uw  = (const float*)d_in[5];  // [8, 384, 64]
    const float* Ub  = (const float*)d_in[6];  // [8, 64]
    const float* Vw  = (const float*)d_in[7];  // [8, 384, 64]
    const float* Vb  = (const float*)d_in[8];  // [8, 64]
    float* out = (float*)d_out;                // [selected(B), log_probs(B), aux(1)]

    k_init<<<1, 32>>>();
    k_gate<<<BB / 8, 256>>>(x, gw, gb);
    k_ev<<<dim3(EE / 16, RR), 256>>>(re, Vw, Vb);
    k_main<<<dim3(BB / 16, RR), 256>>>(x, Uw, Ub);
    k_sample<<<BB, 256>>>(rnd, out);
    k_aux<<<1, 32>>>(out);
}

// round 3
// speedup vs baseline: 1.3567x; 1.3567x over previous
#include <cuda_runtime.h>
#include <math.h>

#define BB 8192
#define DD 384
#define EE 1024
#define RR 8
#define HH 64
#define DPAD 18            // padded smem row (floats): 72B, 8B-aligned, low conflicts
#define GRID_XU 1040       // >= sum_r ceil(cnt[r]/16) <= 1032
#define GRID_MAIN 640      // >= sum_p ceil(pcnt[p]/16) <= 575

typedef unsigned long long ull;

// ---------------- device scratch ----------------
__device__ float g_evt[RR * HH * EE];   // ev transposed [r][h][e]  (2 MB)
__device__ float g_xu[BB * 2 * HH];     // normalized xu per assignment code (4 MB)
__device__ float g_gw[BB * 2];
__device__ int   g_cnt[RR];
__device__ int   g_list[RR * BB];       // router-grouped codes (b*2+k)
__device__ int   g_pcnt[64];
__device__ int   g_plist[64 * BB];      // pair-grouped token ids
__device__ int   g_rtile[GRID_XU];
__device__ int   g_ptile[GRID_MAIN];
__device__ float g_sumP[RR];
__device__ float g_sumM[RR];

// ---------------- f32x2 helpers ----------------
__device__ __forceinline__ ull pk2(float a, float b) {
    ull r; asm("mov.b64 %0, {%1,%2};" : "=l"(r) : "f"(a), "f"(b)); return r;
}
__device__ __forceinline__ void upk2(ull v, float& lo, float& hi) {
    asm("mov.b64 {%0,%1}, %2;" : "=f"(lo), "=f"(hi) : "l"(v));
}
__device__ __forceinline__ ull fma2(ull a, ull b, ull c) {
    ull d; asm("fma.rn.f32x2 %0, %1, %2, %3;" : "=l"(d) : "l"(a), "l"(b), "l"(c)); return d;
}

// ---------------- kernel 0: init ----------------
__global__ void k_init() {
    int t = threadIdx.x;
    if (t < RR) { g_cnt[t] = 0; g_sumP[t] = 0.f; g_sumM[t] = 0.f; }
    if (t < 64) g_pcnt[t] = 0;
}

// ---------------- kernel 1: gate ----------------
__global__ void __launch_bounds__(256) k_gate(const float* __restrict__ x,
                                              const float* __restrict__ gw,
                                              const float* __restrict__ gb) {
    __shared__ float sP[RR], sM[RR];
    int tid = threadIdx.x;
    if (tid < RR) { sP[tid] = 0.f; sM[tid] = 0.f; }
    __syncthreads();

    int warp = tid >> 5, lane = tid & 31;
    int b = blockIdx.x * 8 + warp;

    float acc[RR];
#pragma unroll
    for (int r = 0; r < RR; r++) acc[r] = 0.f;
    const float* xr = x + b * DD;
    for (int d = lane; d < DD; d += 32) {
        float xv = xr[d];
        const float4* g4 = (const float4*)(gw + d * RR);
        float4 a = g4[0], c = g4[1];
        acc[0] += xv * a.x; acc[1] += xv * a.y; acc[2] += xv * a.z; acc[3] += xv * a.w;
        acc[4] += xv * c.x; acc[5] += xv * c.y; acc[6] += xv * c.z; acc[7] += xv * c.w;
    }
#pragma unroll
    for (int r = 0; r < RR; r++)
#pragma unroll
        for (int o = 16; o; o >>= 1) acc[r] += __shfl_xor_sync(0xffffffffu, acc[r], o);

    if (lane == 0) {
        float lg[RR];
#pragma unroll
        for (int r = 0; r < RR; r++) lg[r] = acc[r] + gb[r];
        int i0 = 0; float v0 = lg[0];
#pragma unroll
        for (int r = 1; r < RR; r++) if (lg[r] > v0) { v0 = lg[r]; i0 = r; }
        int i1 = -1; float v1 = -3.0e38f;
#pragma unroll
        for (int r = 0; r < RR; r++) if (r != i0 && lg[r] > v1) { v1 = lg[r]; i1 = r; }

        float s = 0.f, pr[RR];
#pragma unroll
        for (int r = 0; r < RR; r++) { pr[r] = expf(lg[r] - v0); s += pr[r]; }
        float inv = 1.f / s;
#pragma unroll
        for (int r = 0; r < RR; r++) atomicAdd(&sP[r], pr[r] * inv);
        atomicAdd(&sM[i0], 1.f);
        atomicAdd(&sM[i1], 1.f);

        float e1 = expf(v1 - v0);
        float den = 1.f / (1.f + e1);
        g_gw[b * 2 + 0] = den;
        g_gw[b * 2 + 1] = e1 * den;

        int p0 = atomicAdd(&g_cnt[i0], 1); g_list[i0 * BB + p0] = b * 2 + 0;
        int p1 = atomicAdd(&g_cnt[i1], 1); g_list[i1 * BB + p1] = b * 2 + 1;

        int pid = i0 * 8 + i1;
        int pp = atomicAdd(&g_pcnt[pid], 1); g_plist[pid * BB + pp] = b;
    }
    __syncthreads();
    if (tid < RR) { atomicAdd(&g_sumP[tid], sP[tid]); atomicAdd(&g_sumM[tid], sM[tid]); }
}

// ---------------- kernel 2: scheduler (fixed-grid tile maps) ----------------
__global__ void k_sched() {
    int tid = threadIdx.x;
    for (int i = tid; i < GRID_XU; i += 256) g_rtile[i] = -1;
    for (int i = tid; i < GRID_MAIN; i += 256) g_ptile[i] = -1;
    __shared__ int roff[RR], poff[64];
    if (tid == 0) {
        int o = 0;
        for (int r = 0; r < RR; r++) { roff[r] = o; o += (g_cnt[r] + 15) >> 4; }
        o = 0;
        for (int p = 0; p < 64; p++) { poff[p] = o; o += (g_pcnt[p] + 15) >> 4; }
    }
    __syncthreads();
    if (tid < RR) {
        int n = (g_cnt[tid] + 15) >> 4;
        for (int i = 0; i < n; i++) g_rtile[roff[tid] + i] = (tid << 16) | i;
    }
    if (tid >= 64 && tid < 128) {
        int p = tid - 64;
        int n = (g_pcnt[p] + 15) >> 4;
        for (int i = 0; i < n; i++) g_ptile[poff[p] + i] = (p << 16) | i;
    }
}

// ---------------- kernel 3: ev = l2norm(re @ Vw[r] + Vb[r]) -> g_evt[r][h][e] ----------------
__global__ void __launch_bounds__(256) k_ev(const float* __restrict__ re,
                                            const float* __restrict__ Vw,
                                            const float* __restrict__ Vb) {
    __shared__ float sT[DD * DPAD];          // transposed tile [d][e<16]
    __shared__ float pred[4 * HH * 16];      // [dc][h][e]
    __shared__ float srn[16];

    int r = blockIdx.y, ebase = blockIdx.x * 16, tid = threadIdx.x;

    {   // transposed load of re tile
        int t = tid >> 4, c = tid & 15;
        const float* src = re + (ebase + t) * DD;
#pragma unroll
        for (int ch = 0; ch < 6; ch++) {
            int d = ch * 64 + c * 4;
            float4 v = *(const float4*)(src + d);
            sT[(d + 0) * DPAD + t] = v.x; sT[(d + 1) * DPAD + t] = v.y;
            sT[(d + 2) * DPAD + t] = v.z; sT[(d + 3) * DPAD + t] = v.w;
        }
    }
    __syncthreads();

    int hg = tid & 15, eg = (tid >> 4) & 3, dc = tid >> 6;
    ull a[4][2];
#pragma unroll
    for (int i = 0; i < 4; i++) { a[i][0] = 0ULL; a[i][1] = 0ULL; }
    const float* W = Vw + (r * DD + dc * 96) * HH;
#pragma unroll 2
    for (int d = 0; d < 96; d++) {
        float4 u = *(const float4*)(W + d * HH + hg * 4);
        const ull* xr = (const ull*)(&sT[(dc * 96 + d) * DPAD + eg * 4]);
        ull x0 = xr[0], x1 = xr[1];
        ull b0 = pk2(u.x, u.x), b1 = pk2(u.y, u.y), b2 = pk2(u.z, u.z), b3 = pk2(u.w, u.w);
        a[0][0] = fma2(x0, b0, a[0][0]); a[0][1] = fma2(x1, b0, a[0][1]);
        a[1][0] = fma2(x0, b1, a[1][0]); a[1][1] = fma2(x1, b1, a[1][1]);
        a[2][0] = fma2(x0, b2, a[2][0]); a[2][1] = fma2(x1, b2, a[2][1]);
        a[3][0] = fma2(x0, b3, a[3][0]); a[3][1] = fma2(x1, b3, a[3][1]);
    }
#pragma unroll
    for (int i = 0; i < 4; i++) {
        float lo, hi;
        int h = hg * 4 + i;
        upk2(a[i][0], lo, hi);
        pred[(dc * HH + h) * 16 + eg * 4 + 0] = lo;
        pred[(dc * HH + h) * 16 + eg * 4 + 1] = hi;
        upk2(a[i][1], lo, hi);
        pred[(dc * HH + h) * 16 + eg * 4 + 2] = lo;
        pred[(dc * HH + h) * 16 + eg * 4 + 3] = hi;
    }
    __syncthreads();
    {   // reduce d-chunks + bias
        int h = tid >> 2, e0 = (tid & 3) * 4;
        float bias = Vb[r * HH + h];
#pragma unroll
        for (int j = 0; j < 4; j++) {
            float v = pred[h * 16 + e0 + j] + pred[(HH + h) * 16 + e0 + j]
                    + pred[(2 * HH + h) * 16 + e0 + j] + pred[(3 * HH + h) * 16 + e0 + j] + bias;
            pred[h * 16 + e0 + j] = v;
        }
    }
    __syncthreads();
    if (tid < 16) {
        float ss = 0.f;
        for (int h = 0; h < HH; h++) { float v = pred[h * 16 + tid]; ss += v * v; }
        srn[tid] = 1.f / fmaxf(sqrtf(ss), 1e-12f);
    }
    __syncthreads();
    {   // transposed store
        int h = tid >> 2, e0 = (tid & 3) * 4;
        float4 o;
        o.x = pred[h * 16 + e0 + 0] * srn[e0 + 0];
        o.y = pred[h * 16 + e0 + 1] * srn[e0 + 1];
        o.z = pred[h * 16 + e0 + 2] * srn[e0 + 2];
        o.w = pred[h * 16 + e0 + 3] * srn[e0 + 3];
        *(float4*)(g_evt + (r * HH + h) * EE + ebase + e0) = o;
    }
}

// ---------------- kernel 4: xu per assignment -> g_xu[code][h] ----------------
__global__ void __launch_bounds__(256) k_xu(const float* __restrict__ x,
                                            const float* __restrict__ Uw,
                                            const float* __restrict__ Ub) {
    __shared__ float sT[DD * DPAD];
    __shared__ float pred[4 * HH * 16];
    __shared__ float srn[16];
    __shared__ int s_code[16];

    int info = g_rtile[blockIdx.x];
    if (info < 0) return;
    int r = info >> 16, base = (info & 0xffff) * 16;
    int cnt = g_cnt[r];
    int nt = min(16, cnt - base);
    int tid = threadIdx.x;

    if (tid < 16) s_code[tid] = (tid < nt) ? g_list[r * BB + base + tid] : -1;
    __syncthreads();
    {
        int t = tid >> 4, c = tid & 15;
        int code = s_code[t];
        if (code >= 0) {
            const float* src = x + (code >> 1) * DD;
#pragma unroll
            for (int ch = 0; ch < 6; ch++) {
                int d = ch * 64 + c * 4;
                float4 v = *(const float4*)(src + d);
                sT[(d + 0) * DPAD + t] = v.x; sT[(d + 1) * DPAD + t] = v.y;
                sT[(d + 2) * DPAD + t] = v.z; sT[(d + 3) * DPAD + t] = v.w;
            }
        } else {
#pragma unroll
            for (int ch = 0; ch < 6; ch++) {
                int d = ch * 64 + c * 4;
                sT[(d + 0) * DPAD + t] = 0.f; sT[(d + 1) * DPAD + t] = 0.f;
                sT[(d + 2) * DPAD + t] = 0.f; sT[(d + 3) * DPAD + t] = 0.f;
            }
        }
    }
    __syncthreads();

    int hg = tid & 15, eg = (tid >> 4) & 3, dc = tid >> 6;
    ull a[4][2];
#pragma unroll
    for (int i = 0; i < 4; i++) { a[i][0] = 0ULL; a[i][1] = 0ULL; }
    const float* W = Uw + (r * DD + dc * 96) * HH;
#pragma unroll 2
    for (int d = 0; d < 96; d++) {
        float4 u = *(const float4*)(W + d * HH + hg * 4);
        const ull* xr = (const ull*)(&sT[(dc * 96 + d) * DPAD + eg * 4]);
        ull x0 = xr[0], x1 = xr[1];
        ull b0 = pk2(u.x, u.x), b1 = pk2(u.y, u.y), b2 = pk2(u.z, u.z), b3 = pk2(u.w, u.w);
        a[0][0] = fma2(x0, b0, a[0][0]); a[0][1] = fma2(x1, b0, a[0][1]);
        a[1][0] = fma2(x0, b1, a[1][0]); a[1][1] = fma2(x1, b1, a[1][1]);
        a[2][0] = fma2(x0, b2, a[2][0]); a[2][1] = fma2(x1, b2, a[2][1]);
        a[3][0] = fma2(x0, b3, a[3][0]); a[3][1] = fma2(x1, b3, a[3][1]);
    }
#pragma unroll
    for (int i = 0; i < 4; i++) {
        float lo, hi;
        int h = hg * 4 + i;
        upk2(a[i][0], lo, hi);
        pred[(dc * HH + h) * 16 + eg * 4 + 0] = lo;
        pred[(dc * HH + h) * 16 + eg * 4 + 1] = hi;
        upk2(a[i][1], lo, hi);
        pred[(dc * HH + h) * 16 + eg * 4 + 2] = lo;
        pred[(dc * HH + h) * 16 + eg * 4 + 3] = hi;
    }
    __syncthreads();
    {
        int h = tid >> 2, t0 = (tid & 3) * 4;
        float bias = Ub[r * HH + h];
#pragma unroll
        for (int j = 0; j < 4; j++) {
            float v = pred[h * 16 + t0 + j] + pred[(HH + h) * 16 + t0 + j]
                    + pred[(2 * HH + h) * 16 + t0 + j] + pred[(3 * HH + h) * 16 + t0 + j] + bias;
            pred[h * 16 + t0 + j] = v;
        }
    }
    __syncthreads();
    if (tid < 16) {
        float ss = 0.f;
        for (int h = 0; h < HH; h++) { float v = pred[h * 16 + tid]; ss += v * v; }
        srn[tid] = 1.f / fmaxf(sqrtf(ss), 1e-12f);
    }
    __syncthreads();
    {   // write per-code, h-major
        int c = tid >> 4, h0 = (tid & 15) * 4;
        int code = s_code[c];
        if (code >= 0) {
            float rn = srn[c];
            float4 o;
            o.x = pred[(h0 + 0) * 16 + c] * rn;
            o.y = pred[(h0 + 1) * 16 + c] * rn;
            o.z = pred[(h0 + 2) * 16 + c] * rn;
            o.w = pred[(h0 + 3) * 16 + c] * rn;
            *(float4*)(g_xu + code * HH + h0) = o;
        }
    }
}

// ---------------- kernel 5: pair-grouped scores + softmax + combine + sample ----------------
__global__ void __launch_bounds__(256, 2) k_main(const float* __restrict__ rnd,
                                                 float* __restrict__ out) {
    extern __shared__ float dyn[];
    float* p_s = dyn;                            // [16][1024]  64KB
    float* xu_s = dyn + 16 * EE;                 // [2][64][18] 9.2KB
    __shared__ int   s_b[16];
    __shared__ float s_w[2][16];
    __shared__ float red[8][16];
    __shared__ float rowstat[16];
    __shared__ float s_scale[16];

    int info = g_ptile[blockIdx.x];
    if (info < 0) return;
    int pid = info >> 16, base = (info & 0xffff) * 16;
    int r0 = pid >> 3, r1 = pid & 7;
    int cnt = g_pcnt[pid];
    int nt = min(16, cnt - base);
    int tid = threadIdx.x;

    if (tid < 16) {
        int b = (tid < nt) ? g_plist[pid * BB + base + tid] : -1;
        s_b[tid] = b;
        s_w[0][tid] = (b >= 0) ? g_gw[b * 2 + 0] : 0.f;
        s_w[1][tid] = (b >= 0) ? g_gw[b * 2 + 1] : 0.f;
    }
    __syncthreads();
    {   // load xu for both slots, transposed into [h][t]
        int s = tid >> 7, c = (tid >> 3) & 15, h0 = (tid & 7) * 8;
        int b = s_b[c];
        float* dst = xu_s + s * (HH * DPAD);
        if (b >= 0) {
            const float4* src = (const float4*)(g_xu + (b * 2 + s) * HH + h0);
            float4 v0 = src[0], v1 = src[1];
            dst[(h0 + 0) * DPAD + c] = v0.x; dst[(h0 + 1) * DPAD + c] = v0.y;
            dst[(h0 + 2) * DPAD + c] = v0.z; dst[(h0 + 3) * DPAD + c] = v0.w;
            dst[(h0 + 4) * DPAD + c] = v1.x; dst[(h0 + 5) * DPAD + c] = v1.y;
            dst[(h0 + 6) * DPAD + c] = v1.z; dst[(h0 + 7) * DPAD + c] = v1.w;
        } else {
#pragma unroll
            for (int j = 0; j < 8; j++) dst[(h0 + j) * DPAD + c] = 0.f;
        }
    }
    __syncthreads();

    int e0 = tid * 4;
    int lane = tid & 31, w = tid >> 5;

    for (int ph = 0; ph < 2; ph++) {
        int r = ph ? r1 : r0;
        ull acc2[8][4];
#pragma unroll
        for (int tp = 0; tp < 8; tp++)
#pragma unroll
            for (int j = 0; j < 4; j++) acc2[tp][j] = 0ULL;

        const float* evr = g_evt + r * HH * EE;
        const float* xub = xu_s + ph * (HH * DPAD);
#pragma unroll 4
        for (int h = 0; h < HH; h++) {
            float4 ev4 = *(const float4*)(evr + h * EE + e0);
            ull bx = pk2(ev4.x, ev4.x);
            ull by = pk2(ev4.y, ev4.y);
            ull bz = pk2(ev4.z, ev4.z);
            ull bw = pk2(ev4.w, ev4.w);
            const ull* xp = (const ull*)(xub + h * DPAD);
#pragma unroll
            for (int tp = 0; tp < 8; tp++) {
                ull xs = xp[tp];
                acc2[tp][0] = fma2(xs, bx, acc2[tp][0]);
                acc2[tp][1] = fma2(xs, by, acc2[tp][1]);
                acc2[tp][2] = fma2(xs, bz, acc2[tp][2]);
                acc2[tp][3] = fma2(xs, bw, acc2[tp][3]);
            }
        }

        // row max
        {
            float lmax[16];
#pragma unroll
            for (int t = 0; t < 16; t++) lmax[t] = -3.0e38f;
#pragma unroll
            for (int tp = 0; tp < 8; tp++)
#pragma unroll
                for (int j = 0; j < 4; j++) {
                    float lo, hi;
                    upk2(acc2[tp][j], lo, hi);
                    lmax[2 * tp]     = fmaxf(lmax[2 * tp], lo);
                    lmax[2 * tp + 1] = fmaxf(lmax[2 * tp + 1], hi);
                }
#pragma unroll
            for (int t = 0; t < 16; t++)
#pragma unroll
                for (int o = 16; o; o >>= 1)
                    lmax[t] = fmaxf(lmax[t], __shfl_xor_sync(0xffffffffu, lmax[t], o));
            if (lane == 0)
#pragma unroll
                for (int t = 0; t < 16; t++) red[w][t] = lmax[t];
        }
        __syncthreads();
        if (tid < 16) {
            float m = red[0][tid];
#pragma unroll
            for (int ww = 1; ww < 8; ww++) m = fmaxf(m, red[ww][tid]);
            rowstat[tid] = m;
        }
        __syncthreads();

        // exp + row sum
        {
            float lsum[16];
#pragma unroll
            for (int t = 0; t < 16; t++) lsum[t] = 0.f;
#pragma unroll
            for (int tp = 0; tp < 8; tp++) {
                float m0 = rowstat[2 * tp], m1 = rowstat[2 * tp + 1];
#pragma unroll
                for (int j = 0; j < 4; j++) {
                    float lo, hi;
                    upk2(acc2[tp][j], lo, hi);
                    float elo = __expf(lo - m0);
                    float ehi = __expf(hi - m1);
                    lsum[2 * tp]     += elo;
                    lsum[2 * tp + 1] += ehi;
                    acc2[tp][j] = pk2(elo, ehi);
                }
            }
#pragma unroll
            for (int t = 0; t < 16; t++)
#pragma unroll
                for (int o = 16; o; o >>= 1)
                    lsum[t] += __shfl_xor_sync(0xffffffffu, lsum[t], o);
            if (lane == 0)
#pragma unroll
                for (int t = 0; t < 16; t++) red[w][t] = lsum[t];
        }
        __syncthreads();
        if (tid < 16) {
            float s = 0.f;
#pragma unroll
            for (int ww = 0; ww < 8; ww++) s += red[ww][tid];
            s_scale[tid] = s_w[ph][tid] / s;
        }
        __syncthreads();

        // store (ph 0) or combine (ph 1)
#pragma unroll
        for (int tp = 0; tp < 8; tp++) {
            int t0 = 2 * tp, t1 = 2 * tp + 1;
            float sc0 = s_scale[t0], sc1 = s_scale[t1];
            float4 olo, ohi;
            float lo, hi;
            upk2(acc2[tp][0], lo, hi); olo.x = lo * sc0; ohi.x = hi * sc1;
            upk2(acc2[tp][1], lo, hi); olo.y = lo * sc0; ohi.y = hi * sc1;
            upk2(acc2[tp][2], lo, hi); olo.z = lo * sc0; ohi.z = hi * sc1;
            upk2(acc2[tp][3], lo, hi); olo.w = lo * sc0; ohi.w = hi * sc1;
            float4* d0 = (float4*)(p_s + t0 * EE + e0);
            float4* d1 = (float4*)(p_s + t1 * EE + e0);
            if (ph == 0) {
                *d0 = olo; *d1 = ohi;
            } else {
                float4 a = *d0, c = *d1;
                a.x += olo.x; a.y += olo.y; a.z += olo.z; a.w += olo.w;
                c.x += ohi.x; c.y += ohi.y; c.z += ohi.z; c.w += ohi.w;
                *d0 = a; *d1 = c;
            }
        }
        __syncthreads();
    }

    // sampling: warp w handles tokens 2w, 2w+1
#pragma unroll
    for (int k = 0; k < 2; k++) {
        int t = w * 2 + k;
        int b = s_b[t];
        if (b < 0) continue;
        float rv = rnd[b];
        int ebase2 = lane * 32;
        float v[32];
        const float4* pr = (const float4*)(p_s + t * EE + ebase2);
#pragma unroll
        for (int q = 0; q < 8; q++) {
            float4 f = pr[q];
            v[q * 4 + 0] = f.x; v[q * 4 + 1] = f.y; v[q * 4 + 2] = f.z; v[q * 4 + 3] = f.w;
        }
        float lsum = 0.f;
#pragma unroll
        for (int i = 0; i < 32; i++) lsum += v[i];
        float sc = lsum;
#pragma unroll
        for (int o = 1; o < 32; o <<= 1) {
            float u = __shfl_up_sync(0xffffffffu, sc, o);
            if (lane >= o) sc += u;
        }
        float run = sc - lsum;   // exclusive prefix
        int cand = 0x7fffffff;
        float pv = 0.f;
#pragma unroll
        for (int i = 0; i < 32; i++) {
            run += v[i];
            if (cand == 0x7fffffff && run > rv) { cand = ebase2 + i; pv = v[i]; }
        }
        unsigned mask = __ballot_sync(0xffffffffu, cand != 0x7fffffff);
        if (mask == 0) {
            if (lane == 0) { out[b] = 0.f; out[BB + b] = logf(v[0]); }
        } else {
            int firstlane = __ffs(mask) - 1;
            if (lane == firstlane) { out[b] = (float)cand; out[BB + b] = logf(pv); }
        }
    }
}

// ---------------- kernel 6: aux ----------------
__global__ void k_aux(float* __restrict__ out) {
    if (threadIdx.x == 0 && blockIdx.x == 0) {
        float s = 0.f;
#pragma unroll
        for (int r = 0; r < RR; r++) s += g_sumP[r] * g_sumM[r];
        out[2 * BB] = (float)RR * 0.05f * s / ((float)BB * (float)BB);
    }
}

// ---------------- launch ----------------
extern "C" void kernel_launch(void* const* d_in, const int* in_sizes, int n_in,
                              void* d_out, int out_size) {
    const float* x   = (const float*)d_in[0];
    const float* re  = (const float*)d_in[1];
    const float* rnd = (const float*)d_in[2];
    const float* gw  = (const float*)d_in[3];
    const float* gb  = (const float*)d_in[4];
    const float* Uw  = (const float*)d_in[5];
    const float* Ub  = (const float*)d_in[6];
    const float* Vw  = (const float*)d_in[7];
    const float* Vb  = (const float*)d_in[8];
    float* out = (float*)d_out;

    const int dyn_bytes = (16 * EE + 2 * HH * DPAD) * sizeof(float);  // ~74.8KB
    cudaFuncSetAttribute(k_main, cudaFuncAttributeMaxDynamicSharedMemorySize, dyn_bytes);

    k_init<<<1, 128>>>();
    k_gate<<<BB / 8, 256>>>(x, gw, gb);
    k_sched<<<1, 256>>>();
    k_ev<<<dim3(EE / 16, RR), 256>>>(re, Vw, Vb);
    k_xu<<<GRID_XU, 256>>>(x, Uw, Ub);
    k_main<<<GRID_MAIN, 256, dyn_bytes>>>(rnd, out);
    k_aux<<<1, 32>>>(out);
}